// round 17
// baseline (speedup 1.0000x reference)
#include <cuda_runtime.h>
#include <cuda_fp16.h>
#include <cstdint>

// Problem constants
#define BB 64
#define CC 64
#define TT 2000
#define PL 200
#define STRD 100
#define EE 512
#define PP 19
#define NROWS (BB*CC*PP)   // 77824
#define EPSV 1e-5f

// GEMM tiling: 128M x 128N per CTA, 16 warps of 32x32, fp16 k16 MMA
#define BM 128
#define BN 128
#define KSTG 32        // floats per stage = 2 kg of 16
#define NSTAGE 7       // 224 padded K (13 real kg)
#define EPI_PITCH 132  // padded fp32 row pitch for epilogue staging

// fused single-grid block ranges (512 threads each)
#define GEMM_BLOCKS  2432                 // 608 m-tiles x 4 n-tiles
#define STATS_BLOCKS 4864                 // 4864 x 16 warps = 77824 rows
#define MASK_BLOCKS  8                    // 8 x 512 = 4096 rows
#define TOTAL_BLOCKS (GEMM_BLOCKS + STATS_BLOCKS + MASK_BLOCKS)

// smem layout (floats): mainloop bufs [0,16384) ; epi [0,16896) ; stats at 16896
#define SM_STAT_F 16896                   // 256 floats: (mean,inv) per local row
#define SM_WSUM_F (SM_STAT_F + 256)       // 128 floats
#define SM_TOTAL_B ((SM_WSUM_F + 128) * 4)   // 69120 bytes

// ---------------- JAX threefry2x32, partitionable mode ----------------
__device__ __forceinline__ void threefry(uint32_t k0, uint32_t k1,
                                         uint32_t x0, uint32_t x1,
                                         uint32_t& o0, uint32_t& o1) {
    uint32_t ks2 = k0 ^ k1 ^ 0x1BD11BDAu;
    x0 += k0; x1 += k1;
#define TF_RND(r) { x0 += x1; x1 = (x1 << r) | (x1 >> (32 - r)); x1 ^= x0; }
    TF_RND(13) TF_RND(15) TF_RND(26) TF_RND(6)  x0 += k1;  x1 += ks2 + 1u;
    TF_RND(17) TF_RND(29) TF_RND(16) TF_RND(24) x0 += ks2; x1 += k0 + 2u;
    TF_RND(13) TF_RND(15) TF_RND(26) TF_RND(6)  x0 += k0;  x1 += k1 + 3u;
    TF_RND(17) TF_RND(29) TF_RND(16) TF_RND(24) x0 += k1;  x1 += ks2 + 4u;
    TF_RND(13) TF_RND(15) TF_RND(26) TF_RND(6)  x0 += ks2; x1 += k0 + 5u;
#undef TF_RND
    o0 = x0; o1 = x1;
}

__device__ __forceinline__ uint32_t prf32(uint32_t k0, uint32_t k1, uint32_t i) {
    uint32_t o0, o1;
    threefry(k0, k1, 0u, i, o0, o1);
    return o0 ^ o1;
}

__device__ __forceinline__ float u01(uint32_t bits) {
    return __uint_as_float((bits >> 9) | 0x3f800000u) - 1.0f;
}

__device__ void mask_row(int row, float* __restrict__ mout) {
    uint32_t k1a, k1b, k2a, k2b;
    threefry(0u, 42u, 0u, 0u, k1a, k1b);
    threefry(0u, 42u, 0u, 1u, k2a, k2b);

    float r0 = u01(prf32(k2a, k2b, (uint32_t)(row * 3 + 0)));
    float r1 = u01(prf32(k2a, k2b, (uint32_t)(row * 3 + 1)));
    float r2 = u01(prf32(k2a, k2b, (uint32_t)(row * 3 + 2)));

    bool m[PP];
    #pragma unroll
    for (int j = 0; j < PP; ++j)
        m[j] = u01(prf32(k1a, k1b, (uint32_t)(row * PP + j))) < 0.1f;

    if (r0 < 0.5f)  { for (int j = PP - 1; j >= 1; --j) m[j] = m[j] | m[j - 1]; }
    if (r1 < 0.5f)  { for (int j = 0; j < PP - 1; ++j) m[j] = m[j] | m[j + 1]; }
    if (r2 < 0.25f) { for (int j = 0; j < PP - 1; ++j) m[j] = m[j] | m[j + 1]; }

    float* dst = mout + (size_t)row * PP;
    #pragma unroll
    for (int j = 0; j < PP; ++j) dst[j] = m[j] ? 1.0f : 0.0f;
}

// ---------------- fp16 mma helpers ----------------
__device__ __forceinline__ uint32_t packh2(float lo, float hi) {
    __half2 h = __floats2half2_rn(lo, hi);
    return *(uint32_t*)&h;
}

__device__ __forceinline__ void mma_f16_k16(float* d, const uint32_t* a,
                                            const uint32_t* b, const float* c) {
    asm volatile(
        "mma.sync.aligned.m16n8k16.row.col.f32.f16.f16.f32 "
        "{%0,%1,%2,%3}, {%4,%5,%6,%7}, {%8,%9}, {%10,%11,%12,%13};\n"
        : "=f"(d[0]), "=f"(d[1]), "=f"(d[2]), "=f"(d[3])
        : "r"(a[0]), "r"(a[1]), "r"(a[2]), "r"(a[3]),
          "r"(b[0]), "r"(b[1]),
          "f"(c[0]), "f"(c[1]), "f"(c[2]), "f"(c[3]));
}

// ---------------- fused kernel: GEMM + stats + mask in one grid ----------------
__global__ __launch_bounds__(512, 1) void fused_kernel(
    const float* __restrict__ x, const float* __restrict__ W,
    const float* __restrict__ bias, const float* __restrict__ pos,
    const int* __restrict__ subj, const float* __restrict__ gain,
    float* __restrict__ emb, float* __restrict__ patches,
    float* __restrict__ mean_out, float* __restrict__ std_out,
    float* __restrict__ mout)
{
    extern __shared__ uint32_t sm[];
    const int b    = blockIdx.x;
    const int tid  = threadIdx.x;
    const int wid  = tid >> 5;
    const int lane = tid & 31;

    // ===================== stats blocks (one warp per row) =====================
    if (b >= GEMM_BLOCKS && b < GEMM_BLOCKS + STATS_BLOCKS) {
        int warp = (b - GEMM_BLOCKS) * 16 + wid;   // 0..77823
        int bc = warp / PP;
        int p  = warp % PP;
        const float* src = x + (size_t)bc * TT + p * STRD;
        float* dst = patches + (size_t)warp * PL;

        float s = 0.f, s2 = 0.f;
        #pragma unroll
        for (int i = 0; i < 7; ++i) {
            int l = lane + i * 32;
            if (l < PL) {
                float v = src[l];
                s += v; s2 += v * v;
                dst[l] = v;
            }
        }
        #pragma unroll
        for (int off = 16; off; off >>= 1) {
            s  += __shfl_xor_sync(0xffffffffu, s,  off);
            s2 += __shfl_xor_sync(0xffffffffu, s2, off);
        }
        if (lane == 0) {
            float mean = s * (1.f / PL);
            float var  = (s2 - s * mean) * (1.f / (PL - 1));
            mean_out[warp] = mean;
            std_out[warp]  = sqrtf(fmaxf(var, 0.f));
        }
        return;
    }
    // ===================== mask blocks =====================
    if (b >= GEMM_BLOCKS + STATS_BLOCKS) {
        int row = (b - GEMM_BLOCKS - STATS_BLOCKS) * 512 + tid;
        if (row < BB * CC) mask_row(row, mout);
        return;
    }

    // ===================== GEMM block =====================
    uint32_t* smA = sm;           // 8192 u32 (2 buf x 2 kg x 128 x 8)
    uint32_t* smB = sm + 8192;    // 8192 u32
    float* epi   = (float*)sm;    // 128 x 132 fp32 (reused after mainloop)
    float* sstat = (float*)sm + SM_STAT_F;   // 256: (mean,inv) per local row
    float* swsum = (float*)sm + SM_WSUM_F;   // 128

    const int g    = lane >> 2;   // 0..7
    const int tg   = lane & 3;    // 0..3
    const int wm   = wid >> 2;    // 0..3 : 32-row warp tile
    const int wn   = wid & 3;     // 0..3 : 32-col warp tile

    const int row0 = (b >> 2) * BM;
    const int n0   = (b & 3) * BN;

    // loaders: 8 lanes per row x 16B
    const int lrow8 = tid >> 3;    // 0..63 ; covers rows lrow8 and lrow8+64
    const int lq    = tid & 7;
    const int kofs  = lq * 4;
    const int kg_l  = lq >> 2;
    const int ko    = (lq & 3) * 4;
    const int w0    = (ko < 8) ? ko : (ko - 7);

    const float* srcA0;
    const float* srcA1;
    {
        int ar0 = row0 + lrow8;
        int ar1 = row0 + lrow8 + 64;
        srcA0 = x + (size_t)(ar0 / PP) * TT + (ar0 % PP) * STRD + kofs;
        srcA1 = x + (size_t)(ar1 / PP) * TT + (ar1 % PP) * STRD + kofs;
    }
    const float* srcB0 = W + (size_t)(n0 + lrow8) * PL + kofs;
    const float* srcB1 = W + (size_t)(n0 + lrow8 + 64) * PL + kofs;

    float acc[2][4][4];
    #pragma unroll
    for (int mt = 0; mt < 2; ++mt)
        #pragma unroll
        for (int nt = 0; nt < 4; ++nt)
            #pragma unroll
            for (int qq = 0; qq < 4; ++qq) acc[mt][nt][qq] = 0.f;

    // in-CTA stats accumulators
    float sa0 = 0.f, qa0 = 0.f, sa1 = 0.f, qa1 = 0.f;   // A rows: sum, sumsq
    float tb0 = 0.f, tb1 = 0.f;                          // B rows: sum

    // two prefetch register sets (2 stages in flight)
    float4 ca0, ca1, cb0, cb1;
    float4 na0, na1, nb0, nb1;

    ca0 = *(const float4*)srcA0;
    ca1 = *(const float4*)srcA1;
    cb0 = *(const float4*)srcB0;
    cb1 = *(const float4*)srcB1;
    na0 = *(const float4*)(srcA0 + KSTG);
    na1 = *(const float4*)(srcA1 + KSTG);
    nb0 = *(const float4*)(srcB0 + KSTG);
    nb1 = *(const float4*)(srcB1 + KSTG);

    #pragma unroll 1
    for (int s = 0; s < NSTAGE; ++s) {
        const int buf = (s & 1) * 4096;
        // store current stage + accumulate stats (each element seen once)
        {
            uint32_t* da0 = smA + buf + kg_l * 1024 + lrow8 * 8 + w0;
            uint32_t* da1 = smA + buf + kg_l * 1024 + (lrow8 + 64) * 8 + w0;
            uint32_t* db0 = smB + buf + kg_l * 1024 + lrow8 * 8 + w0;
            uint32_t* db1 = smB + buf + kg_l * 1024 + (lrow8 + 64) * 8 + w0;
            da0[0] = packh2(ca0.x, ca0.y); da0[2] = packh2(ca0.z, ca0.w);
            da1[0] = packh2(ca1.x, ca1.y); da1[2] = packh2(ca1.z, ca1.w);
            db0[0] = packh2(cb0.x, cb0.y); db0[2] = packh2(cb0.z, cb0.w);
            db1[0] = packh2(cb1.x, cb1.y); db1[2] = packh2(cb1.z, cb1.w);
            sa0 += ca0.x + ca0.y + ca0.z + ca0.w;
            qa0 += ca0.x*ca0.x + ca0.y*ca0.y + ca0.z*ca0.z + ca0.w*ca0.w;
            sa1 += ca1.x + ca1.y + ca1.z + ca1.w;
            qa1 += ca1.x*ca1.x + ca1.y*ca1.y + ca1.z*ca1.z + ca1.w*ca1.w;
            tb0 += cb0.x + cb0.y + cb0.z + cb0.w;
            tb1 += cb1.x + cb1.y + cb1.z + cb1.w;
        }
        __syncthreads();

        // rotate and prefetch stage s+2
        ca0 = na0; ca1 = na1; cb0 = nb0; cb1 = nb1;
        if (s + 2 < NSTAGE) {
            const int rel = (s + 2) * KSTG;
            const bool ok = (rel + kofs) < PL;
            na0 = ok ? *(const float4*)(srcA0 + rel) : make_float4(0.f,0.f,0.f,0.f);
            na1 = ok ? *(const float4*)(srcA1 + rel) : make_float4(0.f,0.f,0.f,0.f);
            nb0 = ok ? *(const float4*)(srcB0 + rel) : make_float4(0.f,0.f,0.f,0.f);
            nb1 = ok ? *(const float4*)(srcB1 + rel) : make_float4(0.f,0.f,0.f,0.f);
        }

        // compute: kg pair (skip all-zero kg 13 at s==6)
        #pragma unroll
        for (int kg = 0; kg < 2; ++kg) {
            if (s == NSTAGE - 1 && kg == 1) break;
            const uint32_t* ab = smA + buf + kg * 1024;
            const uint32_t* bb = smB + buf + kg * 1024;
            uint32_t af[2][4];
            #pragma unroll
            for (int mt = 0; mt < 2; ++mt) {
                int m = wm * 32 + mt * 16 + g;
                uint2 lo = *(const uint2*)(ab + m * 8 + tg * 2);
                uint2 hi = *(const uint2*)(ab + (m + 8) * 8 + tg * 2);
                af[mt][0] = lo.x; af[mt][1] = hi.x;
                af[mt][2] = lo.y; af[mt][3] = hi.y;
            }
            uint32_t bf[4][2];
            #pragma unroll
            for (int nt = 0; nt < 4; ++nt) {
                int n = wn * 32 + nt * 8 + g;
                uint2 bv = *(const uint2*)(bb + n * 8 + tg * 2);
                bf[nt][0] = bv.x; bf[nt][1] = bv.y;
            }
            #pragma unroll
            for (int mt = 0; mt < 2; ++mt)
                #pragma unroll
                for (int nt = 0; nt < 4; ++nt)
                    mma_f16_k16(acc[mt][nt], af[mt], bf[nt], acc[mt][nt]);
        }
        // single barrier per stage (double buffering covers the rest)
    }

    // reduce stats across the 8 loader lanes of each row group
    #pragma unroll
    for (int off = 4; off; off >>= 1) {
        sa0 += __shfl_xor_sync(0xffffffffu, sa0, off);
        qa0 += __shfl_xor_sync(0xffffffffu, qa0, off);
        sa1 += __shfl_xor_sync(0xffffffffu, sa1, off);
        qa1 += __shfl_xor_sync(0xffffffffu, qa1, off);
        tb0 += __shfl_xor_sync(0xffffffffu, tb0, off);
        tb1 += __shfl_xor_sync(0xffffffffu, tb1, off);
    }
    __syncthreads();   // mainloop smem reads done; safe to overlay epi/stat regions
    if (lq == 0) {
        float m0 = sa0 * (1.f / PL);
        float v0 = (qa0 - sa0 * m0) * (1.f / (PL - 1));
        sstat[lrow8 * 2 + 0] = m0;
        sstat[lrow8 * 2 + 1] = 1.f / (sqrtf(fmaxf(v0, 0.f)) + EPSV);
        float m1 = sa1 * (1.f / PL);
        float v1 = (qa1 - sa1 * m1) * (1.f / (PL - 1));
        sstat[(lrow8 + 64) * 2 + 0] = m1;
        sstat[(lrow8 + 64) * 2 + 1] = 1.f / (sqrtf(fmaxf(v1, 0.f)) + EPSV);
        swsum[lrow8]      = tb0;
        swsum[lrow8 + 64] = tb1;
    }

    // ---- staged epilogue ----
    // 1) raw accumulators -> padded smem tile
    {
        const int dloc = wn * 32 + 2 * tg;
        #pragma unroll
        for (int mt = 0; mt < 2; ++mt) {
            #pragma unroll
            for (int h = 0; h < 2; ++h) {
                int rloc = wm * 32 + mt * 16 + g + h * 8;
                float* erow = epi + rloc * EPI_PITCH + dloc;
                #pragma unroll
                for (int nt = 0; nt < 4; ++nt)
                    *(float2*)(erow + nt * 8) =
                        make_float2(acc[mt][nt][h * 2 + 0], acc[mt][nt][h * 2 + 1]);
            }
        }
    }
    __syncthreads();

    // 2) coalesced fused copy-out
    #pragma unroll
    for (int it = 0; it < 8; ++it) {
        int fid = it * 512 + tid;
        int row = fid >> 5;            // 0..127
        int c4  = (fid & 31) * 4;      // 0..124
        int r   = row0 + row;
        float mv = sstat[row * 2 + 0], iv = sstat[row * 2 + 1];
        float miv = mv * iv;
        int rp  = r % PP;
        int sid = subj[(r / PP) >> 6];
        int d   = n0 + c4;

        float4 a  = *(float4*)&epi[row * EPI_PITCH + c4];
        float4 w4 = *(const float4*)&swsum[c4];
        float4 p4 = *(const float4*)&pos[(size_t)rp * EE + d];
        float4 b4 = *(const float4*)&bias[d];
        float4 g4 = *(const float4*)&gain[(size_t)sid * EE + d];
        float4 o;
        o.x = (iv * a.x - miv * w4.x + p4.x + b4.x) * g4.x;
        o.y = (iv * a.y - miv * w4.y + p4.y + b4.y) * g4.y;
        o.z = (iv * a.z - miv * w4.z + p4.z + b4.z) * g4.z;
        o.w = (iv * a.w - miv * w4.w + p4.w + b4.w) * g4.w;
        *(float4*)&emb[(size_t)r * EE + d] = o;
    }
}

// ---------------- launch ----------------
extern "C" void kernel_launch(void* const* d_in, const int* in_sizes, int n_in,
                              void* d_out, int out_size) {
    const float* x    = (const float*)d_in[0];
    const int*   subj = (const int*)  d_in[1];
    const float* W    = (const float*)d_in[2];
    const float* bias = (const float*)d_in[3];
    const float* pos  = (const float*)d_in[4];
    const float* gain = (const float*)d_in[5];

    float* out      = (float*)d_out;
    float* emb      = out;                               // 77824*512
    float* patches  = emb + (size_t)NROWS * EE;          // 77824*200
    float* mfloat   = patches + (size_t)NROWS * PL;      // 77824
    float* mean_out = mfloat + NROWS;                    // 77824
    float* std_out  = mean_out + NROWS;                  // 77824

    cudaFuncSetAttribute(fused_kernel,
                         cudaFuncAttributeMaxDynamicSharedMemorySize, SM_TOTAL_B);

    fused_kernel<<<TOTAL_BLOCKS, 512, SM_TOTAL_B>>>(
        x, W, bias, pos, subj, gain, emb, patches, mean_out, std_out, mfloat);
}